// round 14
// baseline (speedup 1.0000x reference)
#include <cuda_runtime.h>
#include <cuda_fp16.h>
#include <math.h>
#include <stdint.h>

// ---------------------------------------------------------------------------
// GPT Sparse Transformer Block  (B=2, S=2048, D=1024, H=16, Dh=64, HID=4096)
// Round 13 (= Round 11/12 resubmit after repeated infra failures):
// fp16 m16n8k16 GEMMs; BK=64 (16 k-iters), 3-stage cp.async,
// ONE __syncthreads per k-iter.
// ---------------------------------------------------------------------------

#define D_MODEL 1024
#define N_HEADS 16
#define HEAD_DIM 64
#define HIDDEN 4096
#define SEQ 2048
#define BATCH 2
#define BLK 16
#define M_ROWS (BATCH * SEQ)   // 4096
#define QKV_LD (3 * D_MODEL)   // 3072

// ------------------------- scratch (no allocations allowed) ----------------
__device__ __half g_h   [M_ROWS * D_MODEL];
__device__ __half g_qkv [M_ROWS * QKV_LD];
__device__ __half g_ctx [M_ROWS * D_MODEL];
__device__ float  g_x1  [M_ROWS * D_MODEL];
__device__ __half g_ff  [M_ROWS * HIDDEN];
// fp16 TRANSPOSED weights [N][K]
__device__ __half g_wqkv[QKV_LD * D_MODEL];
__device__ float  g_bqkv[QKV_LD];
__device__ __half g_wo_t[D_MODEL * D_MODEL];
__device__ __half g_w1_t[HIDDEN * D_MODEL];
__device__ __half g_w2_t[D_MODEL * HIDDEN];

// ------------------------------- helpers -----------------------------------
__device__ __forceinline__ void ldsm_x4(uint32_t* r, uint32_t addr) {
    asm volatile("ldmatrix.sync.aligned.m8n8.x4.shared.b16 {%0,%1,%2,%3}, [%4];"
                 : "=r"(r[0]), "=r"(r[1]), "=r"(r[2]), "=r"(r[3]) : "r"(addr));
}
__device__ __forceinline__ void mma_f16(float* d, const uint32_t* a,
                                        uint32_t b0, uint32_t b1) {
    asm volatile(
        "mma.sync.aligned.m16n8k16.row.col.f32.f16.f16.f32 "
        "{%0,%1,%2,%3}, {%4,%5,%6,%7}, {%8,%9}, {%0,%1,%2,%3};"
        : "+f"(d[0]), "+f"(d[1]), "+f"(d[2]), "+f"(d[3])
        : "r"(a[0]), "r"(a[1]), "r"(a[2]), "r"(a[3]), "r"(b0), "r"(b1));
}
__device__ __forceinline__ void cp16(uint32_t s, const void* g) {
    asm volatile("cp.async.cg.shared.global [%0], [%1], 16;" :: "r"(s), "l"(g));
}
__device__ __forceinline__ void cp_commit() { asm volatile("cp.async.commit_group;"); }

// ----------------- weight transpose + fp16 convert kernel --------------------
__global__ void __launch_bounds__(256) trt_kernel(
    const float* __restrict__ src, __half* __restrict__ dst, int K, int N)
{
    __shared__ float t[32][33];
    int n0 = blockIdx.x * 32;
    int k0 = blockIdx.y * 32;
    int tx = threadIdx.x, ty = threadIdx.y;
    #pragma unroll
    for (int r = 0; r < 32; r += 8)
        t[ty + r][tx] = src[(size_t)(k0 + ty + r) * N + n0 + tx];
    __syncthreads();
    #pragma unroll
    for (int r = 0; r < 32; r += 8)
        dst[(size_t)(n0 + ty + r) * K + k0 + tx] = __float2half_rn(t[tx][ty + r]);
}

// ------------------------------- LayerNorm ----------------------------------
__global__ void __launch_bounds__(256) ln_kernel(
    const float* __restrict__ x, const float* __restrict__ gg,
    const float* __restrict__ bb, __half* __restrict__ out)
{
    __shared__ float red[2][8];
    int row = blockIdx.x;
    int tid = threadIdx.x;
    const float4* xr = reinterpret_cast<const float4*>(x + (size_t)row * D_MODEL);
    float4 v = xr[tid];
    float s  = v.x + v.y + v.z + v.w;
    float sq = v.x*v.x + v.y*v.y + v.z*v.z + v.w*v.w;
    #pragma unroll
    for (int o = 16; o; o >>= 1) {
        s  += __shfl_xor_sync(0xFFFFFFFFu, s,  o);
        sq += __shfl_xor_sync(0xFFFFFFFFu, sq, o);
    }
    if ((tid & 31) == 0) { red[0][tid >> 5] = s; red[1][tid >> 5] = sq; }
    __syncthreads();
    if (tid < 32) {
        float a  = (tid < 8) ? red[0][tid] : 0.f;
        float b2 = (tid < 8) ? red[1][tid] : 0.f;
        #pragma unroll
        for (int o = 4; o; o >>= 1) {
            a  += __shfl_xor_sync(0xFFFFFFFFu, a,  o);
            b2 += __shfl_xor_sync(0xFFFFFFFFu, b2, o);
        }
        if (tid == 0) { red[0][0] = a; red[1][0] = b2; }
    }
    __syncthreads();
    float mean = red[0][0] * (1.f / D_MODEL);
    float var  = red[1][0] * (1.f / D_MODEL) - mean * mean;
    float inv  = rsqrtf(var + 1e-5f);
    float4 g4 = reinterpret_cast<const float4*>(gg)[tid];
    float4 b4 = reinterpret_cast<const float4*>(bb)[tid];
    __half2 h01 = __floats2half2_rn((v.x - mean) * inv * g4.x + b4.x,
                                    (v.y - mean) * inv * g4.y + b4.y);
    __half2 h23 = __floats2half2_rn((v.z - mean) * inv * g4.z + b4.z,
                                    (v.w - mean) * inv * g4.w + b4.w);
    __half2* op = reinterpret_cast<__half2*>(out + (size_t)row * D_MODEL + tid * 4);
    op[0] = h01;
    op[1] = h23;
}

// --------------------------- fp16 tensor GEMM --------------------------------
// C[M,N] = A[M,K] @ Bt^T + bias,  A [M][K] fp16, Bt [N][K] fp16.
// EPI 0: bias -> half; 1: bias+res -> float; 2: bias+GELU -> half.
// Block 128x128x64, 8 warps m32n64, 3-stage cp.async, 1 sync/iter.
template <int EPI>
__global__ void __launch_bounds__(256, 2) tgemm_kernel(
    const __half* __restrict__ A, const __half* __restrict__ Bt,
    const float* __restrict__ bias, const float* __restrict__ res,
    void* __restrict__ Cv, int M, int N, int K)
{
    constexpr int BM = 128, BN = 128, BK = 64, STAGES = 3;
    constexpr int LDA = 72;                 // halves; 144B rows, conflict-free
    constexpr int TILE = BM * LDA;          // halves per matrix tile
    extern __shared__ __half sm[];
    __half* As = sm;                        // [STAGES][BM][LDA]
    __half* Bs = sm + STAGES * TILE;        // [STAGES][BN][LDA]

    const int tid  = threadIdx.x;
    const int wid  = tid >> 5;
    const int lane = tid & 31;
    const int bm = blockIdx.y * BM;
    const int bn = blockIdx.x * BN;
    const int wm = (wid >> 1) * 32;
    const int wn = (wid & 1) * 64;

    const int l_row = tid >> 2;             // 0..63 (+64)
    const int l_kc  = (tid & 3) * 8;        // halves; second chunk at +32
    const __half* Ag = A  + (size_t)(bm + l_row) * K + l_kc;
    const __half* Bg = Bt + (size_t)(bn + l_row) * K + l_kc;
    const uint32_t As_b = (uint32_t)__cvta_generic_to_shared(As);
    const uint32_t Bs_b = (uint32_t)__cvta_generic_to_shared(Bs);

    float acc[2][8][4];
    #pragma unroll
    for (int i = 0; i < 2; i++)
        #pragma unroll
        for (int j = 0; j < 8; j++)
            #pragma unroll
            for (int r = 0; r < 4; r++) acc[i][j][r] = 0.f;

    auto load_stage = [&](int stage, int k0) {
        uint32_t Ad = As_b + (uint32_t)(stage * TILE + l_row * LDA + l_kc) * 2;
        uint32_t Bd = Bs_b + (uint32_t)(stage * TILE + l_row * LDA + l_kc) * 2;
        cp16(Ad,                     Ag + k0);
        cp16(Ad + 32 * 2,            Ag + k0 + 32);
        cp16(Ad + 64 * LDA * 2,      Ag + (size_t)64 * K + k0);
        cp16(Ad + (64 * LDA + 32)*2, Ag + (size_t)64 * K + k0 + 32);
        cp16(Bd,                     Bg + k0);
        cp16(Bd + 32 * 2,            Bg + k0 + 32);
        cp16(Bd + 64 * LDA * 2,      Bg + (size_t)64 * K + k0);
        cp16(Bd + (64 * LDA + 32)*2, Bg + (size_t)64 * K + k0 + 32);
    };

    const int NIT = K / BK;                 // 16 for K=1024, 64 for K=4096
    load_stage(0, 0);   cp_commit();
    load_stage(1, BK);  cp_commit();

    const int lr = lane & 15;
    const int lh = lane >> 4;

    for (int it = 0; it < NIT; ++it) {
        asm volatile("cp.async.wait_group 1;");
        __syncthreads();
        // prefetch stage (it+2)%3 == stage (it-1)%3: reads of it-1 completed
        // before this sync, so overwrite is safe with a single barrier.
        if (it + 2 < NIT) { load_stage((it + 2) % STAGES, (it + 2) * BK); }
        cp_commit();

        const uint32_t a_base = As_b + (uint32_t)((it % STAGES) * TILE) * 2;
        const uint32_t b_base = Bs_b + (uint32_t)((it % STAGES) * TILE) * 2;

        #pragma unroll
        for (int ks = 0; ks < 4; ks++) {
            uint32_t af[2][4], bf[4][4];
            #pragma unroll
            for (int mt = 0; mt < 2; mt++)
                ldsm_x4(af[mt], a_base +
                    (uint32_t)((wm + mt * 16 + lr) * LDA + ks * 16 + lh * 8) * 2);
            #pragma unroll
            for (int np = 0; np < 4; np++)
                ldsm_x4(bf[np], b_base +
                    (uint32_t)((wn + np * 16 + lr) * LDA + ks * 16 + lh * 8) * 2);
            #pragma unroll
            for (int mt = 0; mt < 2; mt++) {
                #pragma unroll
                for (int np = 0; np < 4; np++) {
                    mma_f16(acc[mt][2 * np + 0], af[mt], bf[np][0], bf[np][2]);
                    mma_f16(acc[mt][2 * np + 1], af[mt], bf[np][1], bf[np][3]);
                }
            }
        }
    }

    // ---- epilogue ----
    const int qr = lane >> 2;
    const int qc = 2 * (lane & 3);
    #pragma unroll
    for (int mt = 0; mt < 2; mt++) {
        int r0 = bm + wm + mt * 16 + qr;
        #pragma unroll
        for (int nt = 0; nt < 8; nt++) {
            int col = bn + wn + nt * 8 + qc;
            float2 bv = *reinterpret_cast<const float2*>(&bias[col]);
            float v0 = acc[mt][nt][0] + bv.x;
            float v1 = acc[mt][nt][1] + bv.y;
            float v2 = acc[mt][nt][2] + bv.x;
            float v3 = acc[mt][nt][3] + bv.y;
            if (EPI == 1) {
                const float* R = res;
                float2 r0v = *reinterpret_cast<const float2*>(&R[(size_t)r0 * N + col]);
                float2 r1v = *reinterpret_cast<const float2*>(&R[(size_t)(r0 + 8) * N + col]);
                v0 += r0v.x; v1 += r0v.y; v2 += r1v.x; v3 += r1v.y;
                float* C = (float*)Cv;
                *reinterpret_cast<float2*>(&C[(size_t)r0 * N + col])       = make_float2(v0, v1);
                *reinterpret_cast<float2*>(&C[(size_t)(r0 + 8) * N + col]) = make_float2(v2, v3);
            } else {
                if (EPI == 2) {
                    v0 = 0.5f * v0 * (1.f + erff(v0 * 0.70710678118654752f));
                    v1 = 0.5f * v1 * (1.f + erff(v1 * 0.70710678118654752f));
                    v2 = 0.5f * v2 * (1.f + erff(v2 * 0.70710678118654752f));
                    v3 = 0.5f * v3 * (1.f + erff(v3 * 0.70710678118654752f));
                }
                __half* C = (__half*)Cv;
                *reinterpret_cast<__half2*>(&C[(size_t)r0 * N + col]) =
                    __floats2half2_rn(v0, v1);
                *reinterpret_cast<__half2*>(&C[(size_t)(r0 + 8) * N + col]) =
                    __floats2half2_rn(v2, v3);
            }
        }
    }
}

// ---------------------------- sparse attention ------------------------------
__global__ void __launch_bounds__(128) sparse_attn_kernel(
    const __half* __restrict__ QKV, __half* __restrict__ O)
{
    __shared__ float q_s[4][64];
    __shared__ float p_s[4][160];

    int w    = threadIdx.x >> 5;
    int lane = threadIdx.x & 31;
    int gw   = blockIdx.x * 4 + w;
    int i    = gw & (SEQ - 1);
    int bh   = gw >> 11;
    int h    = bh & (N_HEADS - 1);
    int b    = bh >> 4;

    size_t rowq = (size_t)(b * SEQ + i) * QKV_LD + h * HEAD_DIM;
    q_s[w][lane]      = __half2float(QKV[rowq + lane]);
    q_s[w][lane + 32] = __half2float(QKV[rowq + lane + 32]);
    __syncwarp();

    int lb   = i & ~(BLK - 1);
    int nloc = (i & (BLK - 1)) + 1;
    int nsum = i >> 4;
    int nk   = nloc + nsum;

    float sc[5];
    float mymax = -1e30f;
    #pragma unroll
    for (int c = 0; c < 5; c++) {
        int t = lane + c * 32;
        if (t < nk) {
            int j = (t < nloc) ? (lb + t) : (((t - nloc) << 4) + 15);
            const uint4* kp = reinterpret_cast<const uint4*>(
                QKV + (size_t)(b * SEQ + j) * QKV_LD + D_MODEL + h * HEAD_DIM);
            float dot = 0.f;
            #pragma unroll
            for (int d = 0; d < 8; d++) {
                uint4 u = kp[d];
                float2 p0 = __half22float2(*reinterpret_cast<__half2*>(&u.x));
                float2 p1 = __half22float2(*reinterpret_cast<__half2*>(&u.y));
                float2 p2 = __half22float2(*reinterpret_cast<__half2*>(&u.z));
                float2 p3 = __half22float2(*reinterpret_cast<__half2*>(&u.w));
                dot = fmaf(p0.x, q_s[w][d * 8 + 0], dot);
                dot = fmaf(p0.y, q_s[w][d * 8 + 1], dot);
                dot = fmaf(p1.x, q_s[w][d * 8 + 2], dot);
                dot = fmaf(p1.y, q_s[w][d * 8 + 3], dot);
                dot = fmaf(p2.x, q_s[w][d * 8 + 4], dot);
                dot = fmaf(p2.y, q_s[w][d * 8 + 5], dot);
                dot = fmaf(p3.x, q_s[w][d * 8 + 6], dot);
                dot = fmaf(p3.y, q_s[w][d * 8 + 7], dot);
            }
            sc[c] = dot * 0.125f;
            mymax = fmaxf(mymax, sc[c]);
        }
    }
    #pragma unroll
    for (int o = 16; o; o >>= 1)
        mymax = fmaxf(mymax, __shfl_xor_sync(0xFFFFFFFFu, mymax, o));

    float mysum = 0.f;
    #pragma unroll
    for (int c = 0; c < 5; c++) {
        int t = lane + c * 32;
        if (t < nk) { sc[c] = __expf(sc[c] - mymax); mysum += sc[c]; }
    }
    #pragma unroll
    for (int o = 16; o; o >>= 1)
        mysum += __shfl_xor_sync(0xFFFFFFFFu, mysum, o);
    float inv = 1.f / mysum;

    #pragma unroll
    for (int c = 0; c < 5; c++) {
        int t = lane + c * 32;
        if (t < nk) p_s[w][t] = sc[c] * inv;
    }
    __syncwarp();

    float acc0 = 0.f, acc1 = 0.f;
    for (int t = 0; t < nk; t++) {
        int j = (t < nloc) ? (lb + t) : (((t - nloc) << 4) + 15);
        const __half* vp = QKV + (size_t)(b * SEQ + j) * QKV_LD + 2 * D_MODEL + h * HEAD_DIM;
        float p = p_s[w][t];
        acc0 = fmaf(p, __half2float(vp[lane]),      acc0);
        acc1 = fmaf(p, __half2float(vp[lane + 32]), acc1);
    }
    size_t baseo = (size_t)(b * SEQ + i) * D_MODEL + h * HEAD_DIM;
    O[baseo + lane]      = __float2half_rn(acc0);
    O[baseo + lane + 32] = __float2half_rn(acc1);
}

// -------------------------------- launch ------------------------------------
static void* sym_addr(const void* sym) {
    void* p = nullptr;
    cudaGetSymbolAddress(&p, sym);
    return p;
}

extern "C" void kernel_launch(void* const* d_in, const int* in_sizes, int n_in,
                              void* d_out, int out_size)
{
    const float* x     = (const float*)d_in[0];
    const float* ln1_g = (const float*)d_in[1];
    const float* ln1_b = (const float*)d_in[2];
    const float* wq    = (const float*)d_in[3];
    const float* bq    = (const float*)d_in[4];
    const float* wk    = (const float*)d_in[5];
    const float* bk    = (const float*)d_in[6];
    const float* wv    = (const float*)d_in[7];
    const float* bv    = (const float*)d_in[8];
    const float* wo    = (const float*)d_in[9];
    const float* bo    = (const float*)d_in[10];
    const float* ln2_g = (const float*)d_in[11];
    const float* ln2_b = (const float*)d_in[12];
    const float* w1    = (const float*)d_in[13];
    const float* b1    = (const float*)d_in[14];
    const float* w2    = (const float*)d_in[15];
    const float* b2    = (const float*)d_in[16];
    float* out = (float*)d_out;

    __half* p_h    = (__half*)sym_addr(g_h);
    __half* p_qkv  = (__half*)sym_addr(g_qkv);
    __half* p_ctx  = (__half*)sym_addr(g_ctx);
    float*  p_x1   = (float*) sym_addr(g_x1);
    __half* p_ff   = (__half*)sym_addr(g_ff);
    __half* p_wqkv = (__half*)sym_addr(g_wqkv);
    float*  p_bqkv = (float*) sym_addr(g_bqkv);
    __half* p_wo   = (__half*)sym_addr(g_wo_t);
    __half* p_w1   = (__half*)sym_addr(g_w1_t);
    __half* p_w2   = (__half*)sym_addr(g_w2_t);

    const int M = M_ROWS;
    constexpr int SMEM_BYTES = 3 * 2 * 128 * 72 * 2;   // 110,592 B

    cudaFuncSetAttribute(tgemm_kernel<0>, cudaFuncAttributeMaxDynamicSharedMemorySize, SMEM_BYTES);
    cudaFuncSetAttribute(tgemm_kernel<1>, cudaFuncAttributeMaxDynamicSharedMemorySize, SMEM_BYTES);
    cudaFuncSetAttribute(tgemm_kernel<2>, cudaFuncAttributeMaxDynamicSharedMemorySize, SMEM_BYTES);

    // ---- transpose + fp16 weights into [N][K] ----
    dim3 tb(32, 8);
    trt_kernel<<<dim3(D_MODEL / 32, D_MODEL / 32), tb>>>(wq, p_wqkv + 0 * D_MODEL * D_MODEL, D_MODEL, D_MODEL);
    trt_kernel<<<dim3(D_MODEL / 32, D_MODEL / 32), tb>>>(wk, p_wqkv + 1 * D_MODEL * D_MODEL, D_MODEL, D_MODEL);
    trt_kernel<<<dim3(D_MODEL / 32, D_MODEL / 32), tb>>>(wv, p_wqkv + 2 * D_MODEL * D_MODEL, D_MODEL, D_MODEL);
    trt_kernel<<<dim3(D_MODEL / 32, D_MODEL / 32), tb>>>(wo, p_wo, D_MODEL, D_MODEL);
    trt_kernel<<<dim3(HIDDEN / 32,  D_MODEL / 32), tb>>>(w1, p_w1, D_MODEL, HIDDEN);
    trt_kernel<<<dim3(D_MODEL / 32, HIDDEN / 32),  tb>>>(w2, p_w2, HIDDEN, D_MODEL);
    cudaMemcpyAsync(p_bqkv,               bq, D_MODEL * sizeof(float), cudaMemcpyDeviceToDevice, 0);
    cudaMemcpyAsync(p_bqkv + D_MODEL,     bk, D_MODEL * sizeof(float), cudaMemcpyDeviceToDevice, 0);
    cudaMemcpyAsync(p_bqkv + 2 * D_MODEL, bv, D_MODEL * sizeof(float), cudaMemcpyDeviceToDevice, 0);

    // ---- LN1 ----
    ln_kernel<<<M, 256>>>(x, ln1_g, ln1_b, p_h);

    // ---- fused QKV ----
    dim3 gQKV(QKV_LD / 128, M / 128);
    tgemm_kernel<0><<<gQKV, 256, SMEM_BYTES>>>(p_h, p_wqkv, p_bqkv, nullptr,
                                               p_qkv, M, QKV_LD, D_MODEL);

    // ---- sparse attention ----
    sparse_attn_kernel<<<(BATCH * N_HEADS * SEQ) / 4, 128>>>(p_qkv, p_ctx);

    // ---- Wo + residual ----
    dim3 gD(D_MODEL / 128, M / 128);
    tgemm_kernel<1><<<gD, 256, SMEM_BYTES>>>(p_ctx, p_wo, bo, x, p_x1,
                                             M, D_MODEL, D_MODEL);

    // ---- LN2 ----
    ln_kernel<<<M, 256>>>(p_x1, ln2_g, ln2_b, p_h);

    // ---- FFN ----
    dim3 gH(HIDDEN / 128, M / 128);
    tgemm_kernel<2><<<gH, 256, SMEM_BYTES>>>(p_h, p_w1, b1, nullptr, p_ff,
                                             M, HIDDEN, D_MODEL);
    tgemm_kernel<1><<<gD, 256, SMEM_BYTES>>>(p_ff, p_w2, b2, p_x1, out,
                                             M, D_MODEL, HIDDEN);
}

// round 16
// speedup vs baseline: 1.2874x; 1.2874x over previous
#include <cuda_runtime.h>
#include <cuda_fp16.h>
#include <math.h>
#include <stdint.h>

// ---------------------------------------------------------------------------
// GPT Sparse Transformer Block  (B=2, S=2048, D=1024, H=16, Dh=64, HID=4096)
// Round 16 (= Round 15 resubmit after infra failure): GEMM = proven R10
// config (fp16 m16n8k16, BK=32, 4-stage cp.async). Block-shared sparse
// attention — one CTA per (b, h, 16-query block), K/V in smem (16x traffic cut).
// ---------------------------------------------------------------------------

#define D_MODEL 1024
#define N_HEADS 16
#define HEAD_DIM 64
#define HIDDEN 4096
#define SEQ 2048
#define BATCH 2
#define BLK 16
#define M_ROWS (BATCH * SEQ)   // 4096
#define QKV_LD (3 * D_MODEL)   // 3072

// ------------------------- scratch (no allocations allowed) ----------------
__device__ __half g_h   [M_ROWS * D_MODEL];
__device__ __half g_qkv [M_ROWS * QKV_LD];
__device__ __half g_ctx [M_ROWS * D_MODEL];
__device__ float  g_x1  [M_ROWS * D_MODEL];
__device__ __half g_ff  [M_ROWS * HIDDEN];
// fp16 TRANSPOSED weights [N][K]
__device__ __half g_wqkv[QKV_LD * D_MODEL];
__device__ float  g_bqkv[QKV_LD];
__device__ __half g_wo_t[D_MODEL * D_MODEL];
__device__ __half g_w1_t[HIDDEN * D_MODEL];
__device__ __half g_w2_t[D_MODEL * HIDDEN];

// ------------------------------- helpers -----------------------------------
__device__ __forceinline__ void ldsm_x4(uint32_t* r, uint32_t addr) {
    asm volatile("ldmatrix.sync.aligned.m8n8.x4.shared.b16 {%0,%1,%2,%3}, [%4];"
                 : "=r"(r[0]), "=r"(r[1]), "=r"(r[2]), "=r"(r[3]) : "r"(addr));
}
__device__ __forceinline__ void mma_f16(float* d, const uint32_t* a,
                                        uint32_t b0, uint32_t b1) {
    asm volatile(
        "mma.sync.aligned.m16n8k16.row.col.f32.f16.f16.f32 "
        "{%0,%1,%2,%3}, {%4,%5,%6,%7}, {%8,%9}, {%0,%1,%2,%3};"
        : "+f"(d[0]), "+f"(d[1]), "+f"(d[2]), "+f"(d[3])
        : "r"(a[0]), "r"(a[1]), "r"(a[2]), "r"(a[3]), "r"(b0), "r"(b1));
}
__device__ __forceinline__ void cp16(uint32_t s, const void* g) {
    asm volatile("cp.async.cg.shared.global [%0], [%1], 16;" :: "r"(s), "l"(g));
}
__device__ __forceinline__ void cp_commit() { asm volatile("cp.async.commit_group;"); }

// ----------------- weight transpose + fp16 convert kernel --------------------
__global__ void __launch_bounds__(256) trt_kernel(
    const float* __restrict__ src, __half* __restrict__ dst, int K, int N)
{
    __shared__ float t[32][33];
    int n0 = blockIdx.x * 32;
    int k0 = blockIdx.y * 32;
    int tx = threadIdx.x, ty = threadIdx.y;
    #pragma unroll
    for (int r = 0; r < 32; r += 8)
        t[ty + r][tx] = src[(size_t)(k0 + ty + r) * N + n0 + tx];
    __syncthreads();
    #pragma unroll
    for (int r = 0; r < 32; r += 8)
        dst[(size_t)(n0 + ty + r) * K + k0 + tx] = __float2half_rn(t[tx][ty + r]);
}

// ------------------------------- LayerNorm ----------------------------------
__global__ void __launch_bounds__(256) ln_kernel(
    const float* __restrict__ x, const float* __restrict__ gg,
    const float* __restrict__ bb, __half* __restrict__ out)
{
    __shared__ float red[2][8];
    int row = blockIdx.x;
    int tid = threadIdx.x;
    const float4* xr = reinterpret_cast<const float4*>(x + (size_t)row * D_MODEL);
    float4 v = xr[tid];
    float s  = v.x + v.y + v.z + v.w;
    float sq = v.x*v.x + v.y*v.y + v.z*v.z + v.w*v.w;
    #pragma unroll
    for (int o = 16; o; o >>= 1) {
        s  += __shfl_xor_sync(0xFFFFFFFFu, s,  o);
        sq += __shfl_xor_sync(0xFFFFFFFFu, sq, o);
    }
    if ((tid & 31) == 0) { red[0][tid >> 5] = s; red[1][tid >> 5] = sq; }
    __syncthreads();
    if (tid < 32) {
        float a  = (tid < 8) ? red[0][tid] : 0.f;
        float b2 = (tid < 8) ? red[1][tid] : 0.f;
        #pragma unroll
        for (int o = 4; o; o >>= 1) {
            a  += __shfl_xor_sync(0xFFFFFFFFu, a,  o);
            b2 += __shfl_xor_sync(0xFFFFFFFFu, b2, o);
        }
        if (tid == 0) { red[0][0] = a; red[1][0] = b2; }
    }
    __syncthreads();
    float mean = red[0][0] * (1.f / D_MODEL);
    float var  = red[1][0] * (1.f / D_MODEL) - mean * mean;
    float inv  = rsqrtf(var + 1e-5f);
    float4 g4 = reinterpret_cast<const float4*>(gg)[tid];
    float4 b4 = reinterpret_cast<const float4*>(bb)[tid];
    __half2 h01 = __floats2half2_rn((v.x - mean) * inv * g4.x + b4.x,
                                    (v.y - mean) * inv * g4.y + b4.y);
    __half2 h23 = __floats2half2_rn((v.z - mean) * inv * g4.z + b4.z,
                                    (v.w - mean) * inv * g4.w + b4.w);
    __half2* op = reinterpret_cast<__half2*>(out + (size_t)row * D_MODEL + tid * 4);
    op[0] = h01;
    op[1] = h23;
}

// --------------------------- fp16 tensor GEMM (R10 config) -------------------
template <int EPI>
__global__ void __launch_bounds__(256, 2) tgemm_kernel(
    const __half* __restrict__ A, const __half* __restrict__ Bt,
    const float* __restrict__ bias, const float* __restrict__ res,
    void* __restrict__ Cv, int M, int N, int K)
{
    constexpr int BM = 128, BN = 128, BK = 32, STAGES = 4;
    constexpr int LDA = 40;
    constexpr int TILE = BM * LDA;
    extern __shared__ __half sm[];
    __half* As = sm;
    __half* Bs = sm + STAGES * TILE;

    const int tid  = threadIdx.x;
    const int wid  = tid >> 5;
    const int lane = tid & 31;
    const int bm = blockIdx.y * BM;
    const int bn = blockIdx.x * BN;
    const int wm = (wid >> 1) * 32;
    const int wn = (wid & 1) * 64;

    const int l_row = tid >> 2;
    const int l_kc  = (tid & 3) * 8;
    const __half* Ag = A  + (size_t)(bm + l_row) * K + l_kc;
    const __half* Bg = Bt + (size_t)(bn + l_row) * K + l_kc;
    const uint32_t As_b = (uint32_t)__cvta_generic_to_shared(As);
    const uint32_t Bs_b = (uint32_t)__cvta_generic_to_shared(Bs);

    float acc[2][8][4];
    #pragma unroll
    for (int i = 0; i < 2; i++)
        #pragma unroll
        for (int j = 0; j < 8; j++)
            #pragma unroll
            for (int r = 0; r < 4; r++) acc[i][j][r] = 0.f;

    auto load_stage = [&](int stage, int k0) {
        uint32_t Ad = As_b + (uint32_t)(stage * TILE + l_row * LDA + l_kc) * 2;
        uint32_t Bd = Bs_b + (uint32_t)(stage * TILE + l_row * LDA + l_kc) * 2;
        cp16(Ad,                Ag + k0);
        cp16(Ad + 64 * LDA * 2, Ag + (size_t)64 * K + k0);
        cp16(Bd,                Bg + k0);
        cp16(Bd + 64 * LDA * 2, Bg + (size_t)64 * K + k0);
    };

    const int NIT = K / BK;
    load_stage(0, 0);       cp_commit();
    load_stage(1, BK);      cp_commit();
    load_stage(2, 2 * BK);  cp_commit();

    const int lr = lane & 15;
    const int lh = lane >> 4;

    for (int it = 0; it < NIT; ++it) {
        asm volatile("cp.async.wait_group 2;");
        __syncthreads();
        if (it + 3 < NIT) load_stage((it + 3) & 3, (it + 3) * BK);
        cp_commit();

        const uint32_t a_base = As_b + (uint32_t)((it & 3) * TILE) * 2;
        const uint32_t b_base = Bs_b + (uint32_t)((it & 3) * TILE) * 2;

        #pragma unroll
        for (int ks = 0; ks < 2; ks++) {
            uint32_t af[2][4], bf[4][4];
            #pragma unroll
            for (int mt = 0; mt < 2; mt++)
                ldsm_x4(af[mt], a_base +
                    (uint32_t)((wm + mt * 16 + lr) * LDA + ks * 16 + lh * 8) * 2);
            #pragma unroll
            for (int np = 0; np < 4; np++)
                ldsm_x4(bf[np], b_base +
                    (uint32_t)((wn + np * 16 + lr) * LDA + ks * 16 + lh * 8) * 2);
            #pragma unroll
            for (int mt = 0; mt < 2; mt++) {
                #pragma unroll
                for (int np = 0; np < 4; np++) {
                    mma_f16(acc[mt][2 * np + 0], af[mt], bf[np][0], bf[np][2]);
                    mma_f16(acc[mt][2 * np + 1], af[mt], bf[np][1], bf[np][3]);
                }
            }
        }
        __syncthreads();
    }

    // ---- epilogue ----
    const int qr = lane >> 2;
    const int qc = 2 * (lane & 3);
    #pragma unroll
    for (int mt = 0; mt < 2; mt++) {
        int r0 = bm + wm + mt * 16 + qr;
        #pragma unroll
        for (int nt = 0; nt < 8; nt++) {
            int col = bn + wn + nt * 8 + qc;
            float2 bv = *reinterpret_cast<const float2*>(&bias[col]);
            float v0 = acc[mt][nt][0] + bv.x;
            float v1 = acc[mt][nt][1] + bv.y;
            float v2 = acc[mt][nt][2] + bv.x;
            float v3 = acc[mt][nt][3] + bv.y;
            if (EPI == 1) {
                const float* R = res;
                float2 r0v = *reinterpret_cast<const float2*>(&R[(size_t)r0 * N + col]);
                float2 r1v = *reinterpret_cast<const float2*>(&R[(size_t)(r0 + 8) * N + col]);
                v0 += r0v.x; v1 += r0v.y; v2 += r1v.x; v3 += r1v.y;
                float* C = (float*)Cv;
                *reinterpret_cast<float2*>(&C[(size_t)r0 * N + col])       = make_float2(v0, v1);
                *reinterpret_cast<float2*>(&C[(size_t)(r0 + 8) * N + col]) = make_float2(v2, v3);
            } else {
                if (EPI == 2) {
                    v0 = 0.5f * v0 * (1.f + erff(v0 * 0.70710678118654752f));
                    v1 = 0.5f * v1 * (1.f + erff(v1 * 0.70710678118654752f));
                    v2 = 0.5f * v2 * (1.f + erff(v2 * 0.70710678118654752f));
                    v3 = 0.5f * v3 * (1.f + erff(v3 * 0.70710678118654752f));
                }
                __half* C = (__half*)Cv;
                *reinterpret_cast<__half2*>(&C[(size_t)r0 * N + col]) =
                    __floats2half2_rn(v0, v1);
                *reinterpret_cast<__half2*>(&C[(size_t)(r0 + 8) * N + col]) =
                    __floats2half2_rn(v2, v3);
            }
        }
    }
}

// ------------------- block-shared sparse attention ---------------------------
// One CTA per (b, h, qblock of 16 queries). Keys for query i = qb*16+q:
//   summary rows j = 16k+15, k < qb  (shared by all 16 queries)
//   local rows   j = qb*16+t, t <= q
// Key list: [0, qb) = summary, [qb, qb+16) = local.
// Valid keys for query q: idx < qb + q + 1.
#define NKMAX 144
__global__ void __launch_bounds__(128) block_attn_kernel(
    const __half* __restrict__ QKV, __half* __restrict__ O)
{
    extern __shared__ char smraw[];
    float*  Qs = (float*)smraw;                       // [16][68]
    float*  Ps = Qs + 16 * 68;                        // [16][NKMAX]
    __half* Ks = (__half*)(Ps + 16 * NKMAX);          // [NKMAX][64]
    __half* Vs = Ks + NKMAX * 64;                     // [NKMAX][64]

    const int tid = threadIdx.x;
    const int cta = blockIdx.x;
    const int qb = cta & 127;
    const int h  = (cta >> 7) & 15;
    const int b  = cta >> 11;
    const int base_row = b * SEQ + qb * 16;
    const int nsum = qb;
    const int nk = nsum + 16;

    const int q   = tid >> 3;          // 0..15
    const int sub = tid & 7;           // 0..7

    // ---- load Q block (16 x 64) -> fp32 smem ----
    {
        const uint4* src = reinterpret_cast<const uint4*>(
            QKV + (size_t)(base_row + q) * QKV_LD + h * HEAD_DIM) + sub;
        uint4 u = *src;
        __half2* hp = reinterpret_cast<__half2*>(&u);
        float* dq = Qs + q * 68 + sub * 8;
        #pragma unroll
        for (int k = 0; k < 4; k++) {
            float2 f = __half22float2(hp[k]);
            dq[2 * k]     = f.x;
            dq[2 * k + 1] = f.y;
        }
    }
    // ---- load K, V rows (nk x 64 each) ----
    for (int r0 = 0; r0 < nk; r0 += 16) {
        int r = r0 + q;               // q doubles as row-loader index
        if (r < nk) {
            int j = (r < nsum) ? (16 * r + 15) : (qb * 16 + (r - nsum));
            const __half* kb = QKV + (size_t)(b * SEQ + j) * QKV_LD + D_MODEL + h * HEAD_DIM;
            reinterpret_cast<uint4*>(Ks + r * 64)[sub] =
                reinterpret_cast<const uint4*>(kb)[sub];
            reinterpret_cast<uint4*>(Vs + r * 64)[sub] =
                reinterpret_cast<const uint4*>(kb + D_MODEL)[sub];
        }
    }
    __syncthreads();

    // ---- scores + softmax (per query, 8 lanes cooperate) ----
    const int nkq = nsum + q + 1;
    float sc[18];
    float mymax = -1e30f;
    int cnt = 0;
    const float* qq = Qs + q * 68;
    for (int idx = sub; idx < nkq; idx += 8) {
        const uint4* kr = reinterpret_cast<const uint4*>(Ks + idx * 64);
        float dot = 0.f;
        #pragma unroll
        for (int dd = 0; dd < 8; dd++) {
            int d = (dd + sub) & 7;           // stagger -> conflict-free
            uint4 u = kr[d];
            __half2* hp = reinterpret_cast<__half2*>(&u);
            #pragma unroll
            for (int k = 0; k < 4; k++) {
                float2 f = __half22float2(hp[k]);
                dot = fmaf(f.x, qq[d * 8 + 2 * k],     dot);
                dot = fmaf(f.y, qq[d * 8 + 2 * k + 1], dot);
            }
        }
        sc[cnt++] = dot * 0.125f;
        mymax = fmaxf(mymax, dot * 0.125f);
    }
    #pragma unroll
    for (int o = 4; o; o >>= 1)
        mymax = fmaxf(mymax, __shfl_xor_sync(0xFFFFFFFFu, mymax, o));
    float mysum = 0.f;
    cnt = 0;
    for (int idx = sub; idx < nkq; idx += 8) {
        float e = __expf(sc[cnt] - mymax);
        sc[cnt] = e;
        mysum += e;
        cnt++;
    }
    #pragma unroll
    for (int o = 4; o; o >>= 1)
        mysum += __shfl_xor_sync(0xFFFFFFFFu, mysum, o);
    float inv = 1.f / mysum;
    cnt = 0;
    for (int idx = sub; idx < nkq; idx += 8)
        Ps[q * NKMAX + idx] = sc[cnt++] * inv;
    __syncthreads();

    // ---- ctx = P @ V  (thread: query q, dims sub*8 .. sub*8+7) ----
    {
        float acc[8];
        #pragma unroll
        for (int k = 0; k < 8; k++) acc[k] = 0.f;
        const float* pq = Ps + q * NKMAX;
        for (int idx = 0; idx < nkq; idx++) {
            float p = pq[idx];
            uint4 u = *reinterpret_cast<const uint4*>(Vs + idx * 64 + sub * 8);
            __half2* hp = reinterpret_cast<__half2*>(&u);
            #pragma unroll
            for (int k = 0; k < 4; k++) {
                float2 f = __half22float2(hp[k]);
                acc[2 * k]     = fmaf(p, f.x, acc[2 * k]);
                acc[2 * k + 1] = fmaf(p, f.y, acc[2 * k + 1]);
            }
        }
        __half2 o01 = __floats2half2_rn(acc[0], acc[1]);
        __half2 o23 = __floats2half2_rn(acc[2], acc[3]);
        __half2 o45 = __floats2half2_rn(acc[4], acc[5]);
        __half2 o67 = __floats2half2_rn(acc[6], acc[7]);
        __half2* op = reinterpret_cast<__half2*>(
            O + (size_t)(base_row + q) * D_MODEL + h * HEAD_DIM + sub * 8);
        op[0] = o01; op[1] = o23; op[2] = o45; op[3] = o67;
    }
}

// -------------------------------- launch ------------------------------------
static void* sym_addr(const void* sym) {
    void* p = nullptr;
    cudaGetSymbolAddress(&p, sym);
    return p;
}

extern "C" void kernel_launch(void* const* d_in, const int* in_sizes, int n_in,
                              void* d_out, int out_size)
{
    const float* x     = (const float*)d_in[0];
    const float* ln1_g = (const float*)d_in[1];
    const float* ln1_b = (const float*)d_in[2];
    const float* wq    = (const float*)d_in[3];
    const float* bq    = (const float*)d_in[4];
    const float* wk    = (const float*)d_in[5];
    const float* bk    = (const float*)d_in[6];
    const float* wv    = (const float*)d_in[7];
    const float* bv    = (const float*)d_in[8];
    const float* wo    = (const float*)d_in[9];
    const float* bo    = (const float*)d_in[10];
    const float* ln2_g = (const float*)d_in[11];
    const float* ln2_b = (const float*)d_in[12];
    const float* w1    = (const float*)d_in[13];
    const float* b1    = (const float*)d_in[14];
    const float* w2    = (const float*)d_in[15];
    const float* b2    = (const float*)d_in[16];
    float* out = (float*)d_out;

    __half* p_h    = (__half*)sym_addr(g_h);
    __half* p_qkv  = (__half*)sym_addr(g_qkv);
    __half* p_ctx  = (__half*)sym_addr(g_ctx);
    float*  p_x1   = (float*) sym_addr(g_x1);
    __half* p_ff   = (__half*)sym_addr(g_ff);
    __half* p_wqkv = (__half*)sym_addr(g_wqkv);
    float*  p_bqkv = (float*) sym_addr(g_bqkv);
    __half* p_wo   = (__half*)sym_addr(g_wo_t);
    __half* p_w1   = (__half*)sym_addr(g_w1_t);
    __half* p_w2   = (__half*)sym_addr(g_w2_t);

    const int M = M_ROWS;
    constexpr int SMEM_BYTES = 4 * 2 * 128 * 40 * 2;   // 81,920 B (R10 config)
    constexpr int ATTN_SMEM  = (16 * 68 + 16 * NKMAX) * 4 + 2 * NKMAX * 64 * 2;

    cudaFuncSetAttribute(tgemm_kernel<0>, cudaFuncAttributeMaxDynamicSharedMemorySize, SMEM_BYTES);
    cudaFuncSetAttribute(tgemm_kernel<1>, cudaFuncAttributeMaxDynamicSharedMemorySize, SMEM_BYTES);
    cudaFuncSetAttribute(tgemm_kernel<2>, cudaFuncAttributeMaxDynamicSharedMemorySize, SMEM_BYTES);
    cudaFuncSetAttribute(block_attn_kernel, cudaFuncAttributeMaxDynamicSharedMemorySize, ATTN_SMEM);

    // ---- transpose + fp16 weights into [N][K] ----
    dim3 tb(32, 8);
    trt_kernel<<<dim3(D_MODEL / 32, D_MODEL / 32), tb>>>(wq, p_wqkv + 0 * D_MODEL * D_MODEL, D_MODEL, D_MODEL);
    trt_kernel<<<dim3(D_MODEL / 32, D_MODEL / 32), tb>>>(wk, p_wqkv + 1 * D_MODEL * D_MODEL, D_MODEL, D_MODEL);
    trt_kernel<<<dim3(D_MODEL / 32, D_MODEL / 32), tb>>>(wv, p_wqkv + 2 * D_MODEL * D_MODEL, D_MODEL, D_MODEL);
    trt_kernel<<<dim3(D_MODEL / 32, D_MODEL / 32), tb>>>(wo, p_wo, D_MODEL, D_MODEL);
    trt_kernel<<<dim3(HIDDEN / 32,  D_MODEL / 32), tb>>>(w1, p_w1, D_MODEL, HIDDEN);
    trt_kernel<<<dim3(D_MODEL / 32, HIDDEN / 32),  tb>>>(w2, p_w2, HIDDEN, D_MODEL);
    cudaMemcpyAsync(p_bqkv,               bq, D_MODEL * sizeof(float), cudaMemcpyDeviceToDevice, 0);
    cudaMemcpyAsync(p_bqkv + D_MODEL,     bk, D_MODEL * sizeof(float), cudaMemcpyDeviceToDevice, 0);
    cudaMemcpyAsync(p_bqkv + 2 * D_MODEL, bv, D_MODEL * sizeof(float), cudaMemcpyDeviceToDevice, 0);

    // ---- LN1 ----
    ln_kernel<<<M, 256>>>(x, ln1_g, ln1_b, p_h);

    // ---- fused QKV ----
    dim3 gQKV(QKV_LD / 128, M / 128);
    tgemm_kernel<0><<<gQKV, 256, SMEM_BYTES>>>(p_h, p_wqkv, p_bqkv, nullptr,
                                               p_qkv, M, QKV_LD, D_MODEL);

    // ---- block-shared sparse attention ----
    block_attn_kernel<<<BATCH * N_HEADS * (SEQ / BLK), 128, ATTN_SMEM>>>(p_qkv, p_ctx);

    // ---- Wo + residual ----
    dim3 gD(D_MODEL / 128, M / 128);
    tgemm_kernel<1><<<gD, 256, SMEM_BYTES>>>(p_ctx, p_wo, bo, x, p_x1,
                                             M, D_MODEL, D_MODEL);

    // ---- LN2 ----
    ln_kernel<<<M, 256>>>(p_x1, ln2_g, ln2_b, p_h);

    // ---- FFN ----
    dim3 gH(HIDDEN / 128, M / 128);
    tgemm_kernel<2><<<gH, 256, SMEM_BYTES>>>(p_h, p_w1, b1, nullptr, p_ff,
                                             M, HIDDEN, D_MODEL);
    tgemm_kernel<1><<<gD, 256, SMEM_BYTES>>>(p_ff, p_w2, b2, p_x1, out,
                                             M, D_MODEL, HIDDEN);
}

// round 17
// speedup vs baseline: 1.3166x; 1.0226x over previous
#include <cuda_runtime.h>
#include <cuda_fp16.h>
#include <math.h>
#include <stdint.h>

// ---------------------------------------------------------------------------
// GPT Sparse Transformer Block  (B=2, S=2048, D=1024, H=16, Dh=64, HID=4096)
// Round 17: R16 + all weight transposes and bias copies fused into ONE
// prep_kernel launch (9 launches -> 1). GEMM (R10 config) and block-shared
// attention unchanged.
// ---------------------------------------------------------------------------

#define D_MODEL 1024
#define N_HEADS 16
#define HEAD_DIM 64
#define HIDDEN 4096
#define SEQ 2048
#define BATCH 2
#define BLK 16
#define M_ROWS (BATCH * SEQ)   // 4096
#define QKV_LD (3 * D_MODEL)   // 3072

// ------------------------- scratch (no allocations allowed) ----------------
__device__ __half g_h   [M_ROWS * D_MODEL];
__device__ __half g_qkv [M_ROWS * QKV_LD];
__device__ __half g_ctx [M_ROWS * D_MODEL];
__device__ float  g_x1  [M_ROWS * D_MODEL];
__device__ __half g_ff  [M_ROWS * HIDDEN];
// fp16 TRANSPOSED weights [N][K]
__device__ __half g_wqkv[QKV_LD * D_MODEL];
__device__ float  g_bqkv[QKV_LD];
__device__ __half g_wo_t[D_MODEL * D_MODEL];
__device__ __half g_w1_t[HIDDEN * D_MODEL];
__device__ __half g_w2_t[D_MODEL * HIDDEN];

// ------------------------------- helpers -----------------------------------
__device__ __forceinline__ void ldsm_x4(uint32_t* r, uint32_t addr) {
    asm volatile("ldmatrix.sync.aligned.m8n8.x4.shared.b16 {%0,%1,%2,%3}, [%4];"
                 : "=r"(r[0]), "=r"(r[1]), "=r"(r[2]), "=r"(r[3]) : "r"(addr));
}
__device__ __forceinline__ void mma_f16(float* d, const uint32_t* a,
                                        uint32_t b0, uint32_t b1) {
    asm volatile(
        "mma.sync.aligned.m16n8k16.row.col.f32.f16.f16.f32 "
        "{%0,%1,%2,%3}, {%4,%5,%6,%7}, {%8,%9}, {%0,%1,%2,%3};"
        : "+f"(d[0]), "+f"(d[1]), "+f"(d[2]), "+f"(d[3])
        : "r"(a[0]), "r"(a[1]), "r"(a[2]), "r"(a[3]), "r"(b0), "r"(b1));
}
__device__ __forceinline__ void cp16(uint32_t s, const void* g) {
    asm volatile("cp.async.cg.shared.global [%0], [%1], 16;" :: "r"(s), "l"(g));
}
__device__ __forceinline__ void cp_commit() { asm volatile("cp.async.commit_group;"); }

// ------------------- fused prep: 6 transposes + bias concat ------------------
// Tile map (32x32 transpose tiles, block (32,8)):
//   [0,1024)      wq   -> dwqkv + 0
//   [1024,2048)   wk   -> dwqkv + 1M
//   [2048,3072)   wv   -> dwqkv + 2M
//   [3072,4096)   wo   -> dwo
//   [4096,8192)   w1   (K=1024, N=4096) -> dw1
//   [8192,12288)  w2   (K=4096, N=1024) -> dw2
//   [12288,12300) bias concat chunks (256 floats each)
__global__ void __launch_bounds__(256) prep_kernel(
    const float* __restrict__ wq, const float* __restrict__ wk,
    const float* __restrict__ wv, const float* __restrict__ wo,
    const float* __restrict__ w1, const float* __restrict__ w2,
    const float* __restrict__ bq, const float* __restrict__ bk,
    const float* __restrict__ bv,
    __half* __restrict__ dwqkv, __half* __restrict__ dwo,
    __half* __restrict__ dw1,   __half* __restrict__ dw2,
    float* __restrict__ dbqkv)
{
    const int t = blockIdx.x;
    const int tx = threadIdx.x, ty = threadIdx.y;

    if (t >= 12288) {  // bias tiles
        int idx = (t - 12288) * 256 + ty * 32 + tx;
        if (idx < QKV_LD) {
            float v = (idx < D_MODEL) ? bq[idx]
                    : (idx < 2 * D_MODEL) ? bk[idx - D_MODEL]
                    : bv[idx - 2 * D_MODEL];
            dbqkv[idx] = v;
        }
        return;
    }

    const float* src;
    __half* dst;
    int K, N, local;
    if (t < 4096) {
        int m = t >> 10;
        local = t & 1023;
        K = D_MODEL; N = D_MODEL;
        src = (m == 0) ? wq : (m == 1) ? wk : (m == 2) ? wv : wo;
        dst = (m < 3) ? (dwqkv + (size_t)m * D_MODEL * D_MODEL) : dwo;
    } else if (t < 8192) {
        local = t - 4096;
        K = D_MODEL; N = HIDDEN;
        src = w1; dst = dw1;
    } else {
        local = t - 8192;
        K = HIDDEN; N = D_MODEL;
        src = w2; dst = dw2;
    }
    const int tpr = N >> 5;               // tiles per row
    const int n0 = (local % tpr) * 32;
    const int k0 = (local / tpr) * 32;

    __shared__ float tbuf[32][33];
    #pragma unroll
    for (int r = 0; r < 32; r += 8)
        tbuf[ty + r][tx] = src[(size_t)(k0 + ty + r) * N + n0 + tx];
    __syncthreads();
    #pragma unroll
    for (int r = 0; r < 32; r += 8)
        dst[(size_t)(n0 + ty + r) * K + k0 + tx] = __float2half_rn(tbuf[tx][ty + r]);
}

// ------------------------------- LayerNorm ----------------------------------
__global__ void __launch_bounds__(256) ln_kernel(
    const float* __restrict__ x, const float* __restrict__ gg,
    const float* __restrict__ bb, __half* __restrict__ out)
{
    __shared__ float red[2][8];
    int row = blockIdx.x;
    int tid = threadIdx.x;
    const float4* xr = reinterpret_cast<const float4*>(x + (size_t)row * D_MODEL);
    float4 v = xr[tid];
    float s  = v.x + v.y + v.z + v.w;
    float sq = v.x*v.x + v.y*v.y + v.z*v.z + v.w*v.w;
    #pragma unroll
    for (int o = 16; o; o >>= 1) {
        s  += __shfl_xor_sync(0xFFFFFFFFu, s,  o);
        sq += __shfl_xor_sync(0xFFFFFFFFu, sq, o);
    }
    if ((tid & 31) == 0) { red[0][tid >> 5] = s; red[1][tid >> 5] = sq; }
    __syncthreads();
    if (tid < 32) {
        float a  = (tid < 8) ? red[0][tid] : 0.f;
        float b2 = (tid < 8) ? red[1][tid] : 0.f;
        #pragma unroll
        for (int o = 4; o; o >>= 1) {
            a  += __shfl_xor_sync(0xFFFFFFFFu, a,  o);
            b2 += __shfl_xor_sync(0xFFFFFFFFu, b2, o);
        }
        if (tid == 0) { red[0][0] = a; red[1][0] = b2; }
    }
    __syncthreads();
    float mean = red[0][0] * (1.f / D_MODEL);
    float var  = red[1][0] * (1.f / D_MODEL) - mean * mean;
    float inv  = rsqrtf(var + 1e-5f);
    float4 g4 = reinterpret_cast<const float4*>(gg)[tid];
    float4 b4 = reinterpret_cast<const float4*>(bb)[tid];
    __half2 h01 = __floats2half2_rn((v.x - mean) * inv * g4.x + b4.x,
                                    (v.y - mean) * inv * g4.y + b4.y);
    __half2 h23 = __floats2half2_rn((v.z - mean) * inv * g4.z + b4.z,
                                    (v.w - mean) * inv * g4.w + b4.w);
    __half2* op = reinterpret_cast<__half2*>(out + (size_t)row * D_MODEL + tid * 4);
    op[0] = h01;
    op[1] = h23;
}

// --------------------------- fp16 tensor GEMM (R10 config) -------------------
template <int EPI>
__global__ void __launch_bounds__(256, 2) tgemm_kernel(
    const __half* __restrict__ A, const __half* __restrict__ Bt,
    const float* __restrict__ bias, const float* __restrict__ res,
    void* __restrict__ Cv, int M, int N, int K)
{
    constexpr int BM = 128, BN = 128, BK = 32, STAGES = 4;
    constexpr int LDA = 40;
    constexpr int TILE = BM * LDA;
    extern __shared__ __half sm[];
    __half* As = sm;
    __half* Bs = sm + STAGES * TILE;

    const int tid  = threadIdx.x;
    const int wid  = tid >> 5;
    const int lane = tid & 31;
    const int bm = blockIdx.y * BM;
    const int bn = blockIdx.x * BN;
    const int wm = (wid >> 1) * 32;
    const int wn = (wid & 1) * 64;

    const int l_row = tid >> 2;
    const int l_kc  = (tid & 3) * 8;
    const __half* Ag = A  + (size_t)(bm + l_row) * K + l_kc;
    const __half* Bg = Bt + (size_t)(bn + l_row) * K + l_kc;
    const uint32_t As_b = (uint32_t)__cvta_generic_to_shared(As);
    const uint32_t Bs_b = (uint32_t)__cvta_generic_to_shared(Bs);

    float acc[2][8][4];
    #pragma unroll
    for (int i = 0; i < 2; i++)
        #pragma unroll
        for (int j = 0; j < 8; j++)
            #pragma unroll
            for (int r = 0; r < 4; r++) acc[i][j][r] = 0.f;

    auto load_stage = [&](int stage, int k0) {
        uint32_t Ad = As_b + (uint32_t)(stage * TILE + l_row * LDA + l_kc) * 2;
        uint32_t Bd = Bs_b + (uint32_t)(stage * TILE + l_row * LDA + l_kc) * 2;
        cp16(Ad,                Ag + k0);
        cp16(Ad + 64 * LDA * 2, Ag + (size_t)64 * K + k0);
        cp16(Bd,                Bg + k0);
        cp16(Bd + 64 * LDA * 2, Bg + (size_t)64 * K + k0);
    };

    const int NIT = K / BK;
    load_stage(0, 0);       cp_commit();
    load_stage(1, BK);      cp_commit();
    load_stage(2, 2 * BK);  cp_commit();

    const int lr = lane & 15;
    const int lh = lane >> 4;

    for (int it = 0; it < NIT; ++it) {
        asm volatile("cp.async.wait_group 2;");
        __syncthreads();
        if (it + 3 < NIT) load_stage((it + 3) & 3, (it + 3) * BK);
        cp_commit();

        const uint32_t a_base = As_b + (uint32_t)((it & 3) * TILE) * 2;
        const uint32_t b_base = Bs_b + (uint32_t)((it & 3) * TILE) * 2;

        #pragma unroll
        for (int ks = 0; ks < 2; ks++) {
            uint32_t af[2][4], bf[4][4];
            #pragma unroll
            for (int mt = 0; mt < 2; mt++)
                ldsm_x4(af[mt], a_base +
                    (uint32_t)((wm + mt * 16 + lr) * LDA + ks * 16 + lh * 8) * 2);
            #pragma unroll
            for (int np = 0; np < 4; np++)
                ldsm_x4(bf[np], b_base +
                    (uint32_t)((wn + np * 16 + lr) * LDA + ks * 16 + lh * 8) * 2);
            #pragma unroll
            for (int mt = 0; mt < 2; mt++) {
                #pragma unroll
                for (int np = 0; np < 4; np++) {
                    mma_f16(acc[mt][2 * np + 0], af[mt], bf[np][0], bf[np][2]);
                    mma_f16(acc[mt][2 * np + 1], af[mt], bf[np][1], bf[np][3]);
                }
            }
        }
        __syncthreads();
    }

    // ---- epilogue ----
    const int qr = lane >> 2;
    const int qc = 2 * (lane & 3);
    #pragma unroll
    for (int mt = 0; mt < 2; mt++) {
        int r0 = bm + wm + mt * 16 + qr;
        #pragma unroll
        for (int nt = 0; nt < 8; nt++) {
            int col = bn + wn + nt * 8 + qc;
            float2 bv = *reinterpret_cast<const float2*>(&bias[col]);
            float v0 = acc[mt][nt][0] + bv.x;
            float v1 = acc[mt][nt][1] + bv.y;
            float v2 = acc[mt][nt][2] + bv.x;
            float v3 = acc[mt][nt][3] + bv.y;
            if (EPI == 1) {
                const float* R = res;
                float2 r0v = *reinterpret_cast<const float2*>(&R[(size_t)r0 * N + col]);
                float2 r1v = *reinterpret_cast<const float2*>(&R[(size_t)(r0 + 8) * N + col]);
                v0 += r0v.x; v1 += r0v.y; v2 += r1v.x; v3 += r1v.y;
                float* C = (float*)Cv;
                *reinterpret_cast<float2*>(&C[(size_t)r0 * N + col])       = make_float2(v0, v1);
                *reinterpret_cast<float2*>(&C[(size_t)(r0 + 8) * N + col]) = make_float2(v2, v3);
            } else {
                if (EPI == 2) {
                    v0 = 0.5f * v0 * (1.f + erff(v0 * 0.70710678118654752f));
                    v1 = 0.5f * v1 * (1.f + erff(v1 * 0.70710678118654752f));
                    v2 = 0.5f * v2 * (1.f + erff(v2 * 0.70710678118654752f));
                    v3 = 0.5f * v3 * (1.f + erff(v3 * 0.70710678118654752f));
                }
                __half* C = (__half*)Cv;
                *reinterpret_cast<__half2*>(&C[(size_t)r0 * N + col]) =
                    __floats2half2_rn(v0, v1);
                *reinterpret_cast<__half2*>(&C[(size_t)(r0 + 8) * N + col]) =
                    __floats2half2_rn(v2, v3);
            }
        }
    }
}

// ------------------- block-shared sparse attention ---------------------------
#define NKMAX 144
__global__ void __launch_bounds__(128) block_attn_kernel(
    const __half* __restrict__ QKV, __half* __restrict__ O)
{
    extern __shared__ char smraw[];
    float*  Qs = (float*)smraw;                       // [16][68]
    float*  Ps = Qs + 16 * 68;                        // [16][NKMAX]
    __half* Ks = (__half*)(Ps + 16 * NKMAX);          // [NKMAX][64]
    __half* Vs = Ks + NKMAX * 64;                     // [NKMAX][64]

    const int tid = threadIdx.x;
    const int cta = blockIdx.x;
    const int qb = cta & 127;
    const int h  = (cta >> 7) & 15;
    const int b  = cta >> 11;
    const int base_row = b * SEQ + qb * 16;
    const int nsum = qb;
    const int nk = nsum + 16;

    const int q   = tid >> 3;
    const int sub = tid & 7;

    {
        const uint4* src = reinterpret_cast<const uint4*>(
            QKV + (size_t)(base_row + q) * QKV_LD + h * HEAD_DIM) + sub;
        uint4 u = *src;
        __half2* hp = reinterpret_cast<__half2*>(&u);
        float* dq = Qs + q * 68 + sub * 8;
        #pragma unroll
        for (int k = 0; k < 4; k++) {
            float2 f = __half22float2(hp[k]);
            dq[2 * k]     = f.x;
            dq[2 * k + 1] = f.y;
        }
    }
    for (int r0 = 0; r0 < nk; r0 += 16) {
        int r = r0 + q;
        if (r < nk) {
            int j = (r < nsum) ? (16 * r + 15) : (qb * 16 + (r - nsum));
            const __half* kb = QKV + (size_t)(b * SEQ + j) * QKV_LD + D_MODEL + h * HEAD_DIM;
            reinterpret_cast<uint4*>(Ks + r * 64)[sub] =
                reinterpret_cast<const uint4*>(kb)[sub];
            reinterpret_cast<uint4*>(Vs + r * 64)[sub] =
                reinterpret_cast<const uint4*>(kb + D_MODEL)[sub];
        }
    }
    __syncthreads();

    const int nkq = nsum + q + 1;
    float sc[18];
    float mymax = -1e30f;
    int cnt = 0;
    const float* qq = Qs + q * 68;
    for (int idx = sub; idx < nkq; idx += 8) {
        const uint4* kr = reinterpret_cast<const uint4*>(Ks + idx * 64);
        float dot = 0.f;
        #pragma unroll
        for (int dd = 0; dd < 8; dd++) {
            int d = (dd + sub) & 7;
            uint4 u = kr[d];
            __half2* hp = reinterpret_cast<__half2*>(&u);
            #pragma unroll
            for (int k = 0; k < 4; k++) {
                float2 f = __half22float2(hp[k]);
                dot = fmaf(f.x, qq[d * 8 + 2 * k],     dot);
                dot = fmaf(f.y, qq[d * 8 + 2 * k + 1], dot);
            }
        }
        sc[cnt++] = dot * 0.125f;
        mymax = fmaxf(mymax, dot * 0.125f);
    }
    #pragma unroll
    for (int o = 4; o; o >>= 1)
        mymax = fmaxf(mymax, __shfl_xor_sync(0xFFFFFFFFu, mymax, o));
    float mysum = 0.f;
    cnt = 0;
    for (int idx = sub; idx < nkq; idx += 8) {
        float e = __expf(sc[cnt] - mymax);
        sc[cnt] = e;
        mysum += e;
        cnt++;
    }
    #pragma unroll
    for (int o = 4; o; o >>= 1)
        mysum += __shfl_xor_sync(0xFFFFFFFFu, mysum, o);
    float inv = 1.f / mysum;
    cnt = 0;
    for (int idx = sub; idx < nkq; idx += 8)
        Ps[q * NKMAX + idx] = sc[cnt++] * inv;
    __syncthreads();

    {
        float acc[8];
        #pragma unroll
        for (int k = 0; k < 8; k++) acc[k] = 0.f;
        const float* pq = Ps + q * NKMAX;
        for (int idx = 0; idx < nkq; idx++) {
            float p = pq[idx];
            uint4 u = *reinterpret_cast<const uint4*>(Vs + idx * 64 + sub * 8);
            __half2* hp = reinterpret_cast<__half2*>(&u);
            #pragma unroll
            for (int k = 0; k < 4; k++) {
                float2 f = __half22float2(hp[k]);
                acc[2 * k]     = fmaf(p, f.x, acc[2 * k]);
                acc[2 * k + 1] = fmaf(p, f.y, acc[2 * k + 1]);
            }
        }
        __half2 o01 = __floats2half2_rn(acc[0], acc[1]);
        __half2 o23 = __floats2half2_rn(acc[2], acc[3]);
        __half2 o45 = __floats2half2_rn(acc[4], acc[5]);
        __half2 o67 = __floats2half2_rn(acc[6], acc[7]);
        __half2* op = reinterpret_cast<__half2*>(
            O + (size_t)(base_row + q) * D_MODEL + h * HEAD_DIM + sub * 8);
        op[0] = o01; op[1] = o23; op[2] = o45; op[3] = o67;
    }
}

// -------------------------------- launch ------------------------------------
static void* sym_addr(const void* sym) {
    void* p = nullptr;
    cudaGetSymbolAddress(&p, sym);
    return p;
}

extern "C" void kernel_launch(void* const* d_in, const int* in_sizes, int n_in,
                              void* d_out, int out_size)
{
    const float* x     = (const float*)d_in[0];
    const float* ln1_g = (const float*)d_in[1];
    const float* ln1_b = (const float*)d_in[2];
    const float* wq    = (const float*)d_in[3];
    const float* bq    = (const float*)d_in[4];
    const float* wk    = (const float*)d_in[5];
    const float* bk    = (const float*)d_in[6];
    const float* wv    = (const float*)d_in[7];
    const float* bv    = (const float*)d_in[8];
    const float* wo    = (const float*)d_in[9];
    const float* bo    = (const float*)d_in[10];
    const float* ln2_g = (const float*)d_in[11];
    const float* ln2_b = (const float*)d_in[12];
    const float* w1    = (const float*)d_in[13];
    const float* b1    = (const float*)d_in[14];
    const float* w2    = (const float*)d_in[15];
    const float* b2    = (const float*)d_in[16];
    float* out = (float*)d_out;

    __half* p_h    = (__half*)sym_addr(g_h);
    __half* p_qkv  = (__half*)sym_addr(g_qkv);
    __half* p_ctx  = (__half*)sym_addr(g_ctx);
    float*  p_x1   = (float*) sym_addr(g_x1);
    __half* p_ff   = (__half*)sym_addr(g_ff);
    __half* p_wqkv = (__half*)sym_addr(g_wqkv);
    float*  p_bqkv = (float*) sym_addr(g_bqkv);
    __half* p_wo   = (__half*)sym_addr(g_wo_t);
    __half* p_w1   = (__half*)sym_addr(g_w1_t);
    __half* p_w2   = (__half*)sym_addr(g_w2_t);

    const int M = M_ROWS;
    constexpr int SMEM_BYTES = 4 * 2 * 128 * 40 * 2;   // 81,920 B
    constexpr int ATTN_SMEM  = (16 * 68 + 16 * NKMAX) * 4 + 2 * NKMAX * 64 * 2;

    cudaFuncSetAttribute(tgemm_kernel<0>, cudaFuncAttributeMaxDynamicSharedMemorySize, SMEM_BYTES);
    cudaFuncSetAttribute(tgemm_kernel<1>, cudaFuncAttributeMaxDynamicSharedMemorySize, SMEM_BYTES);
    cudaFuncSetAttribute(tgemm_kernel<2>, cudaFuncAttributeMaxDynamicSharedMemorySize, SMEM_BYTES);
    cudaFuncSetAttribute(block_attn_kernel, cudaFuncAttributeMaxDynamicSharedMemorySize, ATTN_SMEM);

    // ---- fused prep: all transposes + bias concat in ONE launch ----
    prep_kernel<<<12300, dim3(32, 8)>>>(wq, wk, wv, wo, w1, w2, bq, bk, bv,
                                        p_wqkv, p_wo, p_w1, p_w2, p_bqkv);

    // ---- LN1 ----
    ln_kernel<<<M, 256>>>(x, ln1_g, ln1_b, p_h);

    // ---- fused QKV ----
    dim3 gQKV(QKV_LD / 128, M / 128);
    tgemm_kernel<0><<<gQKV, 256, SMEM_BYTES>>>(p_h, p_wqkv, p_bqkv, nullptr,
                                               p_qkv, M, QKV_LD, D_MODEL);

    // ---- block-shared sparse attention ----
    block_attn_kernel<<<BATCH * N_HEADS * (SEQ / BLK), 128, ATTN_SMEM>>>(p_qkv, p_ctx);

    // ---- Wo + residual ----
    dim3 gD(D_MODEL / 128, M / 128);
    tgemm_kernel<1><<<gD, 256, SMEM_BYTES>>>(p_ctx, p_wo, bo, x, p_x1,
                                             M, D_MODEL, D_MODEL);

    // ---- LN2 ----
    ln_kernel<<<M, 256>>>(p_x1, ln2_g, ln2_b, p_h);

    // ---- FFN ----
    dim3 gH(HIDDEN / 128, M / 128);
    tgemm_kernel<2><<<gH, 256, SMEM_BYTES>>>(p_h, p_w1, b1, nullptr, p_ff,
                                             M, HIDDEN, D_MODEL);
    tgemm_kernel<1><<<gD, 256, SMEM_BYTES>>>(p_ff, p_w2, b2, p_x1, out,
                                             M, D_MODEL, HIDDEN);
}